// round 2
// baseline (speedup 1.0000x reference)
#include <cuda_runtime.h>
#include <math.h>

#define B_ 4
#define T_ 4096
#define D_ 1024
#define H_ 8
#define K_ 128
#define V_ 128
#define F_ 4096
#define M_ (B_*T_)   // 16384 rows

// ---------------- scratch (device globals; no runtime allocation) ----------------
__device__ float g_n [(size_t)M_*D_];        // ln1 output
__device__ float g_q [(size_t)M_*H_*K_];
__device__ float g_k [(size_t)M_*H_*K_];
__device__ float g_v [(size_t)M_*H_*V_];
__device__ float g_al[(size_t)M_*H_];
__device__ float g_be[(size_t)M_*H_];
__device__ float g_o [(size_t)M_*H_*V_];
__device__ float g_x1[(size_t)M_*D_];        // x + attn
__device__ float g_h [(size_t)M_*D_];        // ln2 output
__device__ float g_f [(size_t)M_*F_];        // FFN intermediate

// ---------------- LayerNorm over D=1024, 256 threads x float4 ----------------
__global__ __launch_bounds__(256) void ln_kernel(const float* __restrict__ x,
    const float* __restrict__ w, const float* __restrict__ bb, float* __restrict__ out)
{
    __shared__ float rs[8], rs2[8];
    int row = blockIdx.x, tid = threadIdx.x;
    const float4* xr = (const float4*)(x + (size_t)row * D_);
    float4 v = xr[tid];
    float s  = v.x + v.y + v.z + v.w;
    float s2 = v.x*v.x + v.y*v.y + v.z*v.z + v.w*v.w;
    #pragma unroll
    for (int m = 16; m; m >>= 1) {
        s  += __shfl_xor_sync(~0u, s,  m);
        s2 += __shfl_xor_sync(~0u, s2, m);
    }
    if ((tid & 31) == 0) { rs[tid>>5] = s; rs2[tid>>5] = s2; }
    __syncthreads();
    s = 0.f; s2 = 0.f;
    #pragma unroll
    for (int i = 0; i < 8; i++) { s += rs[i]; s2 += rs2[i]; }
    float mean = s * (1.0f/D_);
    float var  = s2 * (1.0f/D_) - mean*mean;
    float inv  = rsqrtf(var + 1e-5f);
    float4 wv = ((const float4*)w)[tid];
    float4 bv = ((const float4*)bb)[tid];
    float4 o;
    o.x = (v.x-mean)*inv*wv.x + bv.x;
    o.y = (v.y-mean)*inv*wv.y + bv.y;
    o.z = (v.z-mean)*inv*wv.z + bv.z;
    o.w = (v.w-mean)*inv*wv.w + bv.w;
    ((float4*)(out + (size_t)row * D_))[tid] = o;
}

// ---------------- Tiled SGEMM: C[M,N] = A[M,Kd] @ W[Kd,N] (+epilogue) ----------------
// EPI: 0=none, 1=+resid, 2=+bias then exact GELU, 3=+bias +resid
#define BM 128
#define BN 64
#define BKK 16

template<int EPI>
__global__ __launch_bounds__(256) void sgemm_kernel(
    const float* __restrict__ A, const float* __restrict__ W,
    const float* __restrict__ bias, const float* __restrict__ resid,
    float* __restrict__ C, int M, int N, int Kd)
{
    __shared__ float As[BKK][BM];   // stored transposed: As[k][m]
    __shared__ float Bs[BKK][BN];
    int tid = threadIdx.x;
    int row0 = blockIdx.y * BM;
    int col0 = blockIdx.x * BN;
    int tx = tid & 15, ty = tid >> 4;
    float acc[8][4];
    #pragma unroll
    for (int i = 0; i < 8; i++)
        #pragma unroll
        for (int j = 0; j < 4; j++) acc[i][j] = 0.f;

    for (int k0 = 0; k0 < Kd; k0 += BKK) {
        #pragma unroll
        for (int jj = 0; jj < 2; jj++) {
            int id = tid*2 + jj;
            int ar = id >> 2;
            int ac = (id & 3) << 2;
            float4 av = *(const float4*)(A + (size_t)(row0 + ar)*Kd + k0 + ac);
            As[ac+0][ar] = av.x; As[ac+1][ar] = av.y;
            As[ac+2][ar] = av.z; As[ac+3][ar] = av.w;
        }
        {
            int br = tid >> 4;
            int bc = (tid & 15) << 2;
            *(float4*)(&Bs[br][bc]) = *(const float4*)(W + (size_t)(k0+br)*N + col0 + bc);
        }
        __syncthreads();
        #pragma unroll
        for (int kk = 0; kk < BKK; kk++) {
            float4 a0 = *(const float4*)(&As[kk][ty*8]);
            float4 a1 = *(const float4*)(&As[kk][ty*8+4]);
            float4 b0 = *(const float4*)(&Bs[kk][tx*4]);
            float a[8] = {a0.x,a0.y,a0.z,a0.w,a1.x,a1.y,a1.z,a1.w};
            float b[4] = {b0.x,b0.y,b0.z,b0.w};
            #pragma unroll
            for (int i = 0; i < 8; i++)
                #pragma unroll
                for (int j = 0; j < 4; j++) acc[i][j] = fmaf(a[i], b[j], acc[i][j]);
        }
        __syncthreads();
    }
    #pragma unroll
    for (int i = 0; i < 8; i++) {
        int r = row0 + ty*8 + i;
        int c = col0 + tx*4;
        float4 val = make_float4(acc[i][0], acc[i][1], acc[i][2], acc[i][3]);
        if (EPI == 2 || EPI == 3) {
            float4 bi = *(const float4*)(bias + c);
            val.x += bi.x; val.y += bi.y; val.z += bi.z; val.w += bi.w;
        }
        if (EPI == 2) {  // exact GELU
            val.x = 0.5f*val.x*(1.f + erff(val.x*0.70710678118f));
            val.y = 0.5f*val.y*(1.f + erff(val.y*0.70710678118f));
            val.z = 0.5f*val.z*(1.f + erff(val.z*0.70710678118f));
            val.w = 0.5f*val.w*(1.f + erff(val.w*0.70710678118f));
        }
        if (EPI == 1 || EPI == 3) {
            float4 rv = *(const float4*)(resid + (size_t)r*N + c);
            val.x += rv.x; val.y += rv.y; val.z += rv.z; val.w += rv.w;
        }
        *(float4*)(C + (size_t)r*N + c) = val;
    }
}

// ---------------- alpha/beta: sigmoid(n @ W{a,b}), N=8 each ----------------
__global__ __launch_bounds__(128) void ab_kernel(const float* __restrict__ n,
    const float* __restrict__ Wb, const float* __restrict__ Wa,
    float* __restrict__ al, float* __restrict__ be)
{
    int row = blockIdx.x, tid = threadIdx.x;
    int g = tid >> 3, l = tid & 7;     // 16 groups of 8 lanes
    const float* W = (g < 8) ? Wb : Wa;
    int c = g & 7;
    const float* nr = n + (size_t)row * D_;
    float s = 0.f;
    for (int d = l; d < D_; d += 8) s = fmaf(nr[d], W[d*H_ + c], s);
    s += __shfl_xor_sync(~0u, s, 1);
    s += __shfl_xor_sync(~0u, s, 2);
    s += __shfl_xor_sync(~0u, s, 4);
    if (l == 0) {
        float sig = 1.f/(1.f + expf(-s));
        if (g < 8) be[(size_t)row*H_ + c] = sig;
        else       al[(size_t)row*H_ + c] = sig;
    }
}

// ---------------- silu + l2norm on q,k; silu on v; per (b,t,h) row of 128 ----------------
__global__ __launch_bounds__(128) void act_qkv_kernel(float* __restrict__ q,
    float* __restrict__ kk, float* __restrict__ v)
{
    __shared__ float rq[4], rk[4];
    int row = blockIdx.x, tid = threadIdx.x;
    size_t idx = (size_t)row*128 + tid;
    float xq = q[idx], xk = kk[idx], xv = v[idx];
    float yq = xq / (1.f + expf(-xq));
    float yk = xk / (1.f + expf(-xk));
    float sq = yq*yq, sk2 = yk*yk;
    #pragma unroll
    for (int m = 16; m; m >>= 1) {
        sq  += __shfl_xor_sync(~0u, sq,  m);
        sk2 += __shfl_xor_sync(~0u, sk2, m);
    }
    if ((tid & 31) == 0) { rq[tid>>5] = sq; rk[tid>>5] = sk2; }
    __syncthreads();
    float nq = rq[0]+rq[1]+rq[2]+rq[3];
    float nk = rk[0]+rk[1]+rk[2]+rk[3];
    q[idx]  = yq * rsqrtf(nq + 1e-6f);
    kk[idx] = yk * rsqrtf(nk + 1e-6f);
    v[idx]  = xv / (1.f + expf(-xv));
}

// ---------------- gated delta-rule recurrence ----------------
// grid = B*H*4 blocks (128, single wave). Block handles one (b,h) and 32 of 128
// V-columns for the full T loop. 128 threads: tid -> (col = tid>>2, r4 = tid&3);
// thread owns rows [r4*32, r4*32+32) of its column in registers.
// k/q staged in shared with skew 36 floats per 32-row group -> the 4 same-bank
// addresses (r4=0..3) land on distinct banks; float4 reads stay 16B-aligned
// because 36 floats = 144B = 9*16B.
__global__ __launch_bounds__(128) void recur_kernel(
    const float* __restrict__ q, const float* __restrict__ k, const float* __restrict__ v,
    const float* __restrict__ al, const float* __restrict__ be, float* __restrict__ o)
{
    __shared__ __align__(16) float sk[2][152];
    __shared__ __align__(16) float sq[2][152];
    __shared__ float sv[2][32];
    __shared__ float sab[2][2];

    int blk = blockIdx.x;
    int bh = blk >> 2, split = blk & 3;
    int b = bh >> 3, h = bh & 7;
    int tid = threadIdx.x;
    int col = tid >> 2, r4 = tid & 3;
    int skewIdx = ((tid >> 5) * 36) + (tid & 31);
    int rbase = r4 * 36;
    size_t base  = ((size_t)b * T_ * H_ + h) * (size_t)K_;   // + t*H_*K_ per step
    size_t abase = ((size_t)b * T_) * H_ + h;                // + t*H_ per step

    float S[32];
    #pragma unroll
    for (int i = 0; i < 32; i++) S[i] = 0.f;

    // stage t=0
    sk[0][skewIdx] = k[base + tid];
    sq[0][skewIdx] = q[base + tid];
    if (tid < 32) sv[0][tid] = v[base + split*32 + tid];
    if (tid == 0) { sab[0][0] = al[abase]; sab[0][1] = be[abase]; }
    __syncthreads();

    int buf = 0;
    for (int t = 0; t < T_; t++) {
        // prefetch t+1 into registers (hidden under compute)
        float pk = 0.f, pq = 0.f, pv = 0.f, pa = 0.f, pb = 0.f;
        if (t + 1 < T_) {
            size_t off = base + (size_t)(t+1) * (H_*K_);
            pk = k[off + tid];
            pq = q[off + tid];
            if (tid < 32) pv = v[off + split*32 + tid];
            if (tid == 0) {
                pa = al[abase + (size_t)(t+1)*H_];
                pb = be[abase + (size_t)(t+1)*H_];
            }
        }
        // kS[col] = sum_i k[i] * S[i][col]   (partial over 32 rows, reduce over 4)
        float kreg[32];
        float kv0=0.f,kv1=0.f,kv2=0.f,kv3=0.f;
        #pragma unroll
        for (int i4 = 0; i4 < 8; i4++) {
            float4 k4 = *(const float4*)(&sk[buf][rbase + i4*4]);
            kreg[i4*4+0]=k4.x; kreg[i4*4+1]=k4.y; kreg[i4*4+2]=k4.z; kreg[i4*4+3]=k4.w;
            kv0 = fmaf(k4.x, S[i4*4+0], kv0);
            kv1 = fmaf(k4.y, S[i4*4+1], kv1);
            kv2 = fmaf(k4.z, S[i4*4+2], kv2);
            kv3 = fmaf(k4.w, S[i4*4+3], kv3);
        }
        float kv = (kv0+kv1)+(kv2+kv3);
        kv += __shfl_xor_sync(~0u, kv, 1);
        kv += __shfl_xor_sync(~0u, kv, 2);
        // S = a*S + k * w,  w = b*(v[col] - a*kS[col])
        float a  = sab[buf][0], bt = sab[buf][1];
        float w  = bt * (sv[buf][col] - a * kv);
        #pragma unroll
        for (int i = 0; i < 32; i++) S[i] = fmaf(a, S[i], kreg[i]*w);
        // o[col] = sum_i q[i] * S[i][col]
        float o0=0.f,o1=0.f,o2=0.f,o3=0.f;
        #pragma unroll
        for (int i4 = 0; i4 < 8; i4++) {
            float4 q4 = *(const float4*)(&sq[buf][rbase + i4*4]);
            o0 = fmaf(q4.x, S[i4*4+0], o0);
            o1 = fmaf(q4.y, S[i4*4+1], o1);
            o2 = fmaf(q4.z, S[i4*4+2], o2);
            o3 = fmaf(q4.w, S[i4*4+3], o3);
        }
        float oa = (o0+o1)+(o2+o3);
        oa += __shfl_xor_sync(~0u, oa, 1);
        oa += __shfl_xor_sync(~0u, oa, 2);
        if (r4 == 0) o[base + (size_t)t*(H_*K_) + split*32 + col] = oa;
        // stage t+1
        int nb = buf ^ 1;
        if (t + 1 < T_) {
            sk[nb][skewIdx] = pk;
            sq[nb][skewIdx] = pq;
            if (tid < 32) sv[nb][tid] = pv;
            if (tid == 0) { sab[nb][0] = pa; sab[nb][1] = pb; }
        }
        __syncthreads();
        buf = nb;
    }
}

// ---------------- launch ----------------
extern "C" void kernel_launch(void* const* d_in, const int* in_sizes, int n_in,
                              void* d_out, int out_size)
{
    const float* x    = (const float*)d_in[0];
    const float* Wq   = (const float*)d_in[1];
    const float* Wk   = (const float*)d_in[2];
    const float* Wv   = (const float*)d_in[3];
    const float* Wb   = (const float*)d_in[4];
    const float* Wa   = (const float*)d_in[5];
    const float* Wo   = (const float*)d_in[6];
    const float* ln1w = (const float*)d_in[7];
    const float* ln1b = (const float*)d_in[8];
    const float* ln2w = (const float*)d_in[9];
    const float* ln2b = (const float*)d_in[10];
    const float* W1   = (const float*)d_in[11];
    const float* b1   = (const float*)d_in[12];
    const float* W2   = (const float*)d_in[13];
    const float* b2   = (const float*)d_in[14];
    float* out = (float*)d_out;

    float *n_, *q_, *k_, *v_, *al_, *be_, *o_, *x1_, *h_, *f_;
    cudaGetSymbolAddress((void**)&n_,  g_n);
    cudaGetSymbolAddress((void**)&q_,  g_q);
    cudaGetSymbolAddress((void**)&k_,  g_k);
    cudaGetSymbolAddress((void**)&v_,  g_v);
    cudaGetSymbolAddress((void**)&al_, g_al);
    cudaGetSymbolAddress((void**)&be_, g_be);
    cudaGetSymbolAddress((void**)&o_,  g_o);
    cudaGetSymbolAddress((void**)&x1_, g_x1);
    cudaGetSymbolAddress((void**)&h_,  g_h);
    cudaGetSymbolAddress((void**)&f_,  g_f);

    // 1. ln1
    ln_kernel<<<M_, 256>>>(x, ln1w, ln1b, n_);

    // 2-4. q/k/v raw projections
    dim3 g1(1024/BN, M_/BM);   // (16, 128)
    sgemm_kernel<0><<<g1, 256>>>(n_, Wq, nullptr, nullptr, q_, M_, 1024, 1024);
    sgemm_kernel<0><<<g1, 256>>>(n_, Wk, nullptr, nullptr, k_, M_, 1024, 1024);
    sgemm_kernel<0><<<g1, 256>>>(n_, Wv, nullptr, nullptr, v_, M_, 1024, 1024);

    // 5. alpha/beta
    ab_kernel<<<M_, 128>>>(n_, Wb, Wa, al_, be_);

    // 6. activations + l2norm
    act_qkv_kernel<<<M_*H_, 128>>>(q_, k_, v_);

    // 7. sequential gated delta-rule scan (128 persistent blocks, one wave)
    recur_kernel<<<B_*H_*4, 128>>>(q_, k_, v_, al_, be_, o_);

    // 8. output projection + residual
    sgemm_kernel<1><<<g1, 256>>>(o_, Wo, nullptr, x, x1_, M_, 1024, 1024);

    // 9. ln2
    ln_kernel<<<M_, 256>>>(x1_, ln2w, ln2b, h_);

    // 10-11. FFN
    dim3 g2(4096/BN, M_/BM);   // (64, 128)
    sgemm_kernel<2><<<g2, 256>>>(h_, W1, b1, nullptr, f_, M_, 4096, 1024);
    sgemm_kernel<3><<<g1, 256>>>(f_, W2, b2, x1_, out, M_, 1024, 4096);
}

// round 5
// speedup vs baseline: 1.7697x; 1.7697x over previous
#include <cuda_runtime.h>
#include <cuda_bf16.h>
#include <math.h>
#include <stdint.h>

#define B_ 4
#define T_ 4096
#define D_ 1024
#define H_ 8
#define K_ 128
#define V_ 128
#define F_ 4096
#define M_ (B_*T_)   // 16384 rows

// ---------------- scratch (device globals; no runtime allocation) ----------------
__device__ __align__(128) float g_n [(size_t)M_*D_];
__device__ __align__(128) __nv_bfloat16 g_nhi[(size_t)M_*D_];
__device__ __align__(128) __nv_bfloat16 g_nlo[(size_t)M_*D_];
__device__ __align__(128) float g_q [(size_t)M_*H_*K_];
__device__ __align__(128) float g_k [(size_t)M_*H_*K_];
__device__ __align__(128) float g_v [(size_t)M_*H_*V_];
__device__ __align__(128) float g_al[(size_t)M_*H_];
__device__ __align__(128) float g_be[(size_t)M_*H_];
__device__ __align__(128) float g_o [(size_t)M_*H_*V_];
__device__ __align__(128) __nv_bfloat16 g_ohi[(size_t)M_*H_*V_];
__device__ __align__(128) __nv_bfloat16 g_olo[(size_t)M_*H_*V_];
__device__ __align__(128) float g_x1[(size_t)M_*D_];
__device__ __align__(128) __nv_bfloat16 g_hhi[(size_t)M_*D_];
__device__ __align__(128) __nv_bfloat16 g_hlo[(size_t)M_*D_];
__device__ __align__(128) __nv_bfloat16 g_fhi[(size_t)M_*F_];
__device__ __align__(128) __nv_bfloat16 g_flo[(size_t)M_*F_];
// transposed+split weights ([N,K] K-major)
__device__ __align__(128) __nv_bfloat16 g_wqh[1024*1024], g_wql[1024*1024];
__device__ __align__(128) __nv_bfloat16 g_wkh[1024*1024], g_wkl[1024*1024];
__device__ __align__(128) __nv_bfloat16 g_wvh[1024*1024], g_wvl[1024*1024];
__device__ __align__(128) __nv_bfloat16 g_woh[1024*1024], g_wol[1024*1024];
__device__ __align__(128) __nv_bfloat16 g_w1h[(size_t)4096*1024], g_w1l[(size_t)4096*1024];
__device__ __align__(128) __nv_bfloat16 g_w2h[(size_t)1024*4096], g_w2l[(size_t)1024*4096];

// ======================== PTX helpers ========================
__device__ __forceinline__ uint32_t smem_u32(const void* p) {
    uint32_t a;
    asm("{ .reg .u64 t; cvta.to.shared.u64 t, %1; cvt.u32.u64 %0, t; }" : "=r"(a) : "l"(p));
    return a;
}
__device__ __forceinline__ void cp16(uint32_t s, const void* g) {
    asm volatile("cp.async.cg.shared.global [%0], [%1], 16;\n" :: "r"(s), "l"(g));
}
__device__ __forceinline__ void cp_commit() { asm volatile("cp.async.commit_group;\n" ::: "memory"); }
template<int N> __device__ __forceinline__ void cp_wait() {
    asm volatile("cp.async.wait_group %0;\n" :: "n"(N) : "memory");
}
__device__ __forceinline__ void ldsm4(uint32_t& r0, uint32_t& r1, uint32_t& r2, uint32_t& r3, uint32_t addr) {
    asm volatile("ldmatrix.sync.aligned.m8n8.x4.shared.b16 {%0,%1,%2,%3}, [%4];"
        : "=r"(r0), "=r"(r1), "=r"(r2), "=r"(r3) : "r"(addr));
}
__device__ __forceinline__ void mma16816(float* d, const uint32_t* a, const uint32_t* b) {
    asm volatile("mma.sync.aligned.m16n8k16.row.col.f32.bf16.bf16.f32 "
        "{%0,%1,%2,%3},{%4,%5,%6,%7},{%8,%9},{%0,%1,%2,%3};"
        : "+f"(d[0]), "+f"(d[1]), "+f"(d[2]), "+f"(d[3])
        : "r"(a[0]), "r"(a[1]), "r"(a[2]), "r"(a[3]), "r"(b[0]), "r"(b[1]));
}

// ======================== HMMA GEMM ========================
// C[M,N] = A[M,Kd] @ W[Kd,N]; A as hi/lo bf16 [M,Kd]; B transposed [N,Kd] hi/lo.
// 3-MMA compensated bf16. Tiles: 128x128x32, 8 warps (4m x 2n), warp tile 32x64.
// Smem rows padded to 80B (5x16B) -> ldmatrix 8-row phases conflict-free.
// EPI: 0=plain fp32, 1=+resid, 2=+bias+GELU -> bf16 hi/lo, 3=+bias+resid
#define ROWB 80                      // padded row bytes (32 bf16 data = 64B + 16B pad)
#define ARR_B (128*ROWB)             // 10240 B per array
#define STG_B (4*ARR_B)              // 40960 B per stage
#define NSTAGE 3
#define DSMEM_SZ (NSTAGE*STG_B + 1024)

template<int EPI>
__global__ __launch_bounds__(256, 1) void tc_gemm(
    const __nv_bfloat16* __restrict__ Ahi, const __nv_bfloat16* __restrict__ Alo,
    const __nv_bfloat16* __restrict__ Bhi, const __nv_bfloat16* __restrict__ Blo,
    const float* __restrict__ bias, const float* __restrict__ resid,
    float* __restrict__ C, __nv_bfloat16* __restrict__ Chi, __nv_bfloat16* __restrict__ Clo,
    int M, int N, int Kd)
{
    extern __shared__ __align__(1024) char dsm_raw[];
    const int tid = threadIdx.x;
    const int wid = tid >> 5, lane = tid & 31;
    const int row0 = blockIdx.y * 128;
    const int col0 = blockIdx.x * 128;
    const int NC = Kd >> 5;              // chunks of 32 K-elements

    uint32_t sbase = smem_u32(dsm_raw);
    sbase = (sbase + 1023) & ~1023u;

    // warp tiling: 4m x 2n
    const int wm0 = (wid >> 1) * 32;     // warp m offset in tile
    const int wn0 = (wid & 1) * 64;      // warp n offset in tile

    float acc[2][8][4];
    #pragma unroll
    for (int i = 0; i < 2; i++)
        #pragma unroll
        for (int j = 0; j < 8; j++)
            #pragma unroll
            for (int r = 0; r < 4; r++) acc[i][j][r] = 0.f;

    // per-chunk cooperative load: 4 arrays x 128 rows x 64B data (80B pitch)
    auto load_chunk = [&](int c) {
        const int kb = c << 5;           // K element base
        const uint32_t sb = sbase + (c % NSTAGE) * STG_B;
        #pragma unroll
        for (int arr = 0; arr < 4; arr++) {
            const __nv_bfloat16* src = (arr == 0) ? Ahi : (arr == 1) ? Alo : (arr == 2) ? Bhi : Blo;
            const int rb = (arr < 2) ? row0 : col0;
            #pragma unroll
            for (int i2 = 0; i2 < 2; i2++) {
                int idx = tid + i2 * 256;            // 0..511
                int row = idx >> 2, seg = idx & 3;
                cp16(sb + arr * ARR_B + row * ROWB + seg * 16,
                     src + (size_t)(rb + row) * Kd + kb + seg * 8);
            }
        }
        cp_commit();
    };

    load_chunk(0);
    load_chunk(1);

    const int sub = lane >> 3, r8 = lane & 7;

    for (int c = 0; c < NC; c++) {
        if (c + 2 < NC) load_chunk(c + 2);
        if (c + 2 < NC) cp_wait<2>();
        else if (c + 1 < NC) cp_wait<1>();
        else cp_wait<0>();
        __syncthreads();

        const uint32_t sb = sbase + (c % NSTAGE) * STG_B;
        #pragma unroll
        for (int kk = 0; kk < 2; kk++) {             // two k16 steps per chunk
            const int kbyte = kk * 32;
            // A fragments: 2 m16 tiles x {hi,lo}
            uint32_t ah[2][4], al_[2][4];
            #pragma unroll
            for (int mi = 0; mi < 2; mi++) {
                int row = wm0 + mi * 16 + (sub & 1) * 8 + r8;
                uint32_t off = row * ROWB + kbyte + (sub >> 1) * 16;
                ldsm4(ah[mi][0], ah[mi][1], ah[mi][2], ah[mi][3], sb + off);
                ldsm4(al_[mi][0], al_[mi][1], al_[mi][2], al_[mi][3], sb + ARR_B + off);
            }
            // B fragments: 8 n8 tiles x {hi,lo}, loaded as 4 x4-pairs each
            uint32_t bh[8][2], bl[8][2];
            #pragma unroll
            for (int nj = 0; nj < 4; nj++) {
                int row = wn0 + nj * 16 + (sub >> 1) * 8 + r8;
                uint32_t off = row * ROWB + kbyte + (sub & 1) * 16;
                ldsm4(bh[nj*2][0], bh[nj*2][1], bh[nj*2+1][0], bh[nj*2+1][1], sb + 2*ARR_B + off);
                ldsm4(bl[nj*2][0], bl[nj*2][1], bl[nj*2+1][0], bl[nj*2+1][1], sb + 3*ARR_B + off);
            }
            #pragma unroll
            for (int mi = 0; mi < 2; mi++)
                #pragma unroll
                for (int ni = 0; ni < 8; ni++) {
                    mma16816(acc[mi][ni], ah[mi],  bh[ni]);
                    mma16816(acc[mi][ni], ah[mi],  bl[ni]);
                    mma16816(acc[mi][ni], al_[mi], bh[ni]);
                }
        }
        __syncthreads();
    }

    // ---------------- epilogue ----------------
    const int bcol = col0 + wn0;
    float2 bv[8];
    if (EPI == 2 || EPI == 3) {
        #pragma unroll
        for (int ni = 0; ni < 8; ni++)
            bv[ni] = *(const float2*)(bias + bcol + ni * 8 + (lane & 3) * 2);
    }
    #pragma unroll
    for (int mi = 0; mi < 2; mi++) {
        #pragma unroll
        for (int hf = 0; hf < 2; hf++) {
            const int row = row0 + wm0 + mi * 16 + (lane >> 2) + hf * 8;
            #pragma unroll
            for (int ni = 0; ni < 8; ni++) {
                const int col = bcol + ni * 8 + (lane & 3) * 2;
                float y0 = acc[mi][ni][hf * 2];
                float y1 = acc[mi][ni][hf * 2 + 1];
                if (EPI == 2 || EPI == 3) { y0 += bv[ni].x; y1 += bv[ni].y; }
                if (EPI == 2) {
                    y0 = 0.5f * y0 * (1.f + erff(y0 * 0.70710678118f));
                    y1 = 0.5f * y1 * (1.f + erff(y1 * 0.70710678118f));
                }
                if (EPI == 1 || EPI == 3) {
                    float2 rv = *(const float2*)(resid + (size_t)row * N + col);
                    y0 += rv.x; y1 += rv.y;
                }
                if (EPI == 2) {
                    __nv_bfloat16 h0 = __float2bfloat16(y0);
                    __nv_bfloat16 h1 = __float2bfloat16(y1);
                    __nv_bfloat162 hh(h0, h1);
                    __nv_bfloat162 ll(__float2bfloat16(y0 - __bfloat162float(h0)),
                                      __float2bfloat16(y1 - __bfloat162float(h1)));
                    *(uint32_t*)(Chi + (size_t)row * N + col) = *(uint32_t*)&hh;
                    *(uint32_t*)(Clo + (size_t)row * N + col) = *(uint32_t*)&ll;
                } else {
                    *(float2*)(C + (size_t)row * N + col) = make_float2(y0, y1);
                }
            }
        }
    }
}

// ---------------- LayerNorm (MODE 1: fp32 + split, MODE 2: split only) ----------------
template<int MODE>
__global__ __launch_bounds__(256) void ln_kernel(const float* __restrict__ x,
    const float* __restrict__ w, const float* __restrict__ bb,
    float* __restrict__ out, __nv_bfloat16* __restrict__ ohi, __nv_bfloat16* __restrict__ olo)
{
    __shared__ float rs[8], rs2[8];
    int row = blockIdx.x, tid = threadIdx.x;
    const float4* xr = (const float4*)(x + (size_t)row * D_);
    float4 v = xr[tid];
    float s  = v.x + v.y + v.z + v.w;
    float s2 = v.x*v.x + v.y*v.y + v.z*v.z + v.w*v.w;
    #pragma unroll
    for (int m = 16; m; m >>= 1) {
        s  += __shfl_xor_sync(~0u, s,  m);
        s2 += __shfl_xor_sync(~0u, s2, m);
    }
    if ((tid & 31) == 0) { rs[tid>>5] = s; rs2[tid>>5] = s2; }
    __syncthreads();
    s = 0.f; s2 = 0.f;
    #pragma unroll
    for (int i = 0; i < 8; i++) { s += rs[i]; s2 += rs2[i]; }
    float mean = s * (1.0f/D_);
    float var  = s2 * (1.0f/D_) - mean*mean;
    float inv  = rsqrtf(var + 1e-5f);
    float4 wv = ((const float4*)w)[tid];
    float4 bv = ((const float4*)bb)[tid];
    float o[4];
    o[0] = (v.x-mean)*inv*wv.x + bv.x;
    o[1] = (v.y-mean)*inv*wv.y + bv.y;
    o[2] = (v.z-mean)*inv*wv.z + bv.z;
    o[3] = (v.w-mean)*inv*wv.w + bv.w;
    if (MODE == 1)
        ((float4*)(out + (size_t)row * D_))[tid] = make_float4(o[0],o[1],o[2],o[3]);
    uint32_t hp[2], lp[2];
    #pragma unroll
    for (int p = 0; p < 2; p++) {
        __nv_bfloat16 h0 = __float2bfloat16(o[2*p]);
        __nv_bfloat16 h1 = __float2bfloat16(o[2*p+1]);
        __nv_bfloat162 hh(h0, h1);
        __nv_bfloat162 ll(__float2bfloat16(o[2*p]   - __bfloat162float(h0)),
                          __float2bfloat16(o[2*p+1] - __bfloat162float(h1)));
        hp[p] = *(uint32_t*)&hh; lp[p] = *(uint32_t*)&ll;
    }
    ((uint2*)(ohi + (size_t)row * D_))[tid] = make_uint2(hp[0], hp[1]);
    ((uint2*)(olo + (size_t)row * D_))[tid] = make_uint2(lp[0], lp[1]);
}

// ---------------- weight transpose + split: W[K,N] -> hiT/loT [N,K] ----------------
__global__ __launch_bounds__(256) void wsplitT(const float* __restrict__ W,
    __nv_bfloat16* __restrict__ hiT, __nv_bfloat16* __restrict__ loT, int Kd, int N)
{
    __shared__ float t[32][33];
    int n0 = blockIdx.x * 32, k0 = blockIdx.y * 32;
    int tx = threadIdx.x & 31, ty = threadIdx.x >> 5;
    #pragma unroll
    for (int i = 0; i < 4; i++)
        t[ty + 8*i][tx] = W[(size_t)(k0 + ty + 8*i) * N + n0 + tx];
    __syncthreads();
    #pragma unroll
    for (int i = 0; i < 4; i++) {
        float vv = t[tx][ty + 8*i];
        __nv_bfloat16 h = __float2bfloat16(vv);
        size_t off = (size_t)(n0 + ty + 8*i) * Kd + k0 + tx;
        hiT[off] = h;
        loT[off] = __float2bfloat16(vv - __bfloat162float(h));
    }
}

// ---------------- elementwise split ----------------
__global__ __launch_bounds__(256) void split_kernel(const float* __restrict__ x,
    __nv_bfloat16* __restrict__ hi, __nv_bfloat16* __restrict__ lo, int n4)
{
    int i = blockIdx.x * 256 + threadIdx.x;
    if (i >= n4) return;
    float4 v = ((const float4*)x)[i];
    float o[4] = {v.x, v.y, v.z, v.w};
    uint32_t hp[2], lp[2];
    #pragma unroll
    for (int p = 0; p < 2; p++) {
        __nv_bfloat16 h0 = __float2bfloat16(o[2*p]);
        __nv_bfloat16 h1 = __float2bfloat16(o[2*p+1]);
        __nv_bfloat162 hh(h0, h1);
        __nv_bfloat162 ll(__float2bfloat16(o[2*p]   - __bfloat162float(h0)),
                          __float2bfloat16(o[2*p+1] - __bfloat162float(h1)));
        hp[p] = *(uint32_t*)&hh; lp[p] = *(uint32_t*)&ll;
    }
    ((uint2*)hi)[i] = make_uint2(hp[0], hp[1]);
    ((uint2*)lo)[i] = make_uint2(lp[0], lp[1]);
}

// ---------------- alpha/beta: sigmoid(n @ W{a,b}), N=8 each ----------------
__global__ __launch_bounds__(128) void ab_kernel(const float* __restrict__ n,
    const float* __restrict__ Wb, const float* __restrict__ Wa,
    float* __restrict__ al, float* __restrict__ be)
{
    int row = blockIdx.x, tid = threadIdx.x;
    int g = tid >> 3, l = tid & 7;
    const float* W = (g < 8) ? Wb : Wa;
    int c = g & 7;
    const float* nr = n + (size_t)row * D_;
    float s = 0.f;
    for (int d = l; d < D_; d += 8) s = fmaf(nr[d], W[d*H_ + c], s);
    s += __shfl_xor_sync(~0u, s, 1);
    s += __shfl_xor_sync(~0u, s, 2);
    s += __shfl_xor_sync(~0u, s, 4);
    if (l == 0) {
        float sig = 1.f/(1.f + expf(-s));
        if (g < 8) be[(size_t)row*H_ + c] = sig;
        else       al[(size_t)row*H_ + c] = sig;
    }
}

// ---------------- silu + l2norm on q,k; silu on v ----------------
__global__ __launch_bounds__(128) void act_qkv_kernel(float* __restrict__ q,
    float* __restrict__ kk, float* __restrict__ v)
{
    __shared__ float rq[4], rk[4];
    int row = blockIdx.x, tid = threadIdx.x;
    size_t idx = (size_t)row*128 + tid;
    float xq = q[idx], xk = kk[idx], xv = v[idx];
    float yq = xq / (1.f + expf(-xq));
    float yk = xk / (1.f + expf(-xk));
    float sq = yq*yq, sk2 = yk*yk;
    #pragma unroll
    for (int m = 16; m; m >>= 1) {
        sq  += __shfl_xor_sync(~0u, sq,  m);
        sk2 += __shfl_xor_sync(~0u, sk2, m);
    }
    if ((tid & 31) == 0) { rq[tid>>5] = sq; rk[tid>>5] = sk2; }
    __syncthreads();
    float nq = rq[0]+rq[1]+rq[2]+rq[3];
    float nk = rk[0]+rk[1]+rk[2]+rk[3];
    q[idx]  = yq * rsqrtf(nq + 1e-6f);
    kk[idx] = yk * rsqrtf(nk + 1e-6f);
    v[idx]  = xv / (1.f + expf(-xv));
}

// ---------------- gated delta-rule recurrence ----------------
__global__ __launch_bounds__(128) void recur_kernel(
    const float* __restrict__ q, const float* __restrict__ k, const float* __restrict__ v,
    const float* __restrict__ al, const float* __restrict__ be, float* __restrict__ o)
{
    __shared__ __align__(16) float sk[2][152];
    __shared__ __align__(16) float sq[2][152];
    __shared__ float sv[2][32];
    __shared__ float sab[2][2];

    int blk = blockIdx.x;
    int bh = blk >> 2, split = blk & 3;
    int b = bh >> 3, h = bh & 7;
    int tid = threadIdx.x;
    int col = tid >> 2, r4 = tid & 3;
    int skewIdx = ((tid >> 5) * 36) + (tid & 31);
    int rbase = r4 * 36;
    size_t base  = ((size_t)b * T_ * H_ + h) * (size_t)K_;
    size_t abase = ((size_t)b * T_) * H_ + h;

    float S[32];
    #pragma unroll
    for (int i = 0; i < 32; i++) S[i] = 0.f;

    sk[0][skewIdx] = k[base + tid];
    sq[0][skewIdx] = q[base + tid];
    if (tid < 32) sv[0][tid] = v[base + split*32 + tid];
    if (tid == 0) { sab[0][0] = al[abase]; sab[0][1] = be[abase]; }
    __syncthreads();

    int buf = 0;
    for (int t = 0; t < T_; t++) {
        float pk = 0.f, pq = 0.f, pv = 0.f, pa = 0.f, pb = 0.f;
        if (t + 1 < T_) {
            size_t off = base + (size_t)(t+1) * (H_*K_);
            pk = k[off + tid];
            pq = q[off + tid];
            if (tid < 32) pv = v[off + split*32 + tid];
            if (tid == 0) {
                pa = al[abase + (size_t)(t+1)*H_];
                pb = be[abase + (size_t)(t+1)*H_];
            }
        }
        float kreg[32];
        float kv0=0.f,kv1=0.f,kv2=0.f,kv3=0.f;
        #pragma unroll
        for (int i4 = 0; i4 < 8; i4++) {
            float4 k4 = *(const float4*)(&sk[buf][rbase + i4*4]);
            kreg[i4*4+0]=k4.x; kreg[i4*4+1]=k4.y; kreg[i4*4+2]=k4.z; kreg[i4*4+3]=k4.w;
            kv0 = fmaf(k4.x, S[i4*4+0], kv0);
            kv1 = fmaf(k4.y, S[i4*4+1], kv1);
            kv2 = fmaf(k4.z, S[i4*4+2], kv2);
            kv3 = fmaf(k4.w, S[i4*4+3], kv3);
        }
        float kv = (kv0+kv1)+(kv2+kv3);
        kv += __shfl_xor_sync(~0u, kv, 1);
        kv += __shfl_xor_sync(~0u, kv, 2);
        float a  = sab[buf][0], bt = sab[buf][1];
        float w  = bt * (sv[buf][col] - a * kv);
        #pragma unroll
        for (int i = 0; i < 32; i++) S[i] = fmaf(a, S[i], kreg[i]*w);
        float o0=0.f,o1=0.f,o2=0.f,o3=0.f;
        #pragma unroll
        for (int i4 = 0; i4 < 8; i4++) {
            float4 q4 = *(const float4*)(&sq[buf][rbase + i4*4]);
            o0 = fmaf(q4.x, S[i4*4+0], o0);
            o1 = fmaf(q4.y, S[i4*4+1], o1);
            o2 = fmaf(q4.z, S[i4*4+2], o2);
            o3 = fmaf(q4.w, S[i4*4+3], o3);
        }
        float oa = (o0+o1)+(o2+o3);
        oa += __shfl_xor_sync(~0u, oa, 1);
        oa += __shfl_xor_sync(~0u, oa, 2);
        if (r4 == 0) o[base + (size_t)t*(H_*K_) + split*32 + col] = oa;
        int nb = buf ^ 1;
        if (t + 1 < T_) {
            sk[nb][skewIdx] = pk;
            sq[nb][skewIdx] = pq;
            if (tid < 32) sv[nb][tid] = pv;
            if (tid == 0) { sab[nb][0] = pa; sab[nb][1] = pb; }
        }
        __syncthreads();
        buf = nb;
    }
}

// ---------------- launch ----------------
extern "C" void kernel_launch(void* const* d_in, const int* in_sizes, int n_in,
                              void* d_out, int out_size)
{
    const float* x    = (const float*)d_in[0];
    const float* Wq   = (const float*)d_in[1];
    const float* Wk   = (const float*)d_in[2];
    const float* Wv   = (const float*)d_in[3];
    const float* Wb   = (const float*)d_in[4];
    const float* Wa   = (const float*)d_in[5];
    const float* Wo   = (const float*)d_in[6];
    const float* ln1w = (const float*)d_in[7];
    const float* ln1b = (const float*)d_in[8];
    const float* ln2w = (const float*)d_in[9];
    const float* ln2b = (const float*)d_in[10];
    const float* W1   = (const float*)d_in[11];
    const float* b1   = (const float*)d_in[12];
    const float* W2   = (const float*)d_in[13];
    const float* b2   = (const float*)d_in[14];
    float* out = (float*)d_out;

    float *n_, *q_, *k_, *v_, *al_, *be_, *o_, *x1_;
    __nv_bfloat16 *nhi, *nlo, *ohi, *olo, *hhi, *hlo, *fhi, *flo;
    __nv_bfloat16 *wqh,*wql,*wkh,*wkl,*wvh,*wvl,*woh,*wol,*w1h,*w1l,*w2h,*w2l;
    cudaGetSymbolAddress((void**)&n_,  g_n);
    cudaGetSymbolAddress((void**)&nhi, g_nhi);
    cudaGetSymbolAddress((void**)&nlo, g_nlo);
    cudaGetSymbolAddress((void**)&q_,  g_q);
    cudaGetSymbolAddress((void**)&k_,  g_k);
    cudaGetSymbolAddress((void**)&v_,  g_v);
    cudaGetSymbolAddress((void**)&al_, g_al);
    cudaGetSymbolAddress((void**)&be_, g_be);
    cudaGetSymbolAddress((void**)&o_,  g_o);
    cudaGetSymbolAddress((void**)&ohi, g_ohi);
    cudaGetSymbolAddress((void**)&olo, g_olo);
    cudaGetSymbolAddress((void**)&x1_, g_x1);
    cudaGetSymbolAddress((void**)&hhi, g_hhi);
    cudaGetSymbolAddress((void**)&hlo, g_hlo);
    cudaGetSymbolAddress((void**)&fhi, g_fhi);
    cudaGetSymbolAddress((void**)&flo, g_flo);
    cudaGetSymbolAddress((void**)&wqh, g_wqh); cudaGetSymbolAddress((void**)&wql, g_wql);
    cudaGetSymbolAddress((void**)&wkh, g_wkh); cudaGetSymbolAddress((void**)&wkl, g_wkl);
    cudaGetSymbolAddress((void**)&wvh, g_wvh); cudaGetSymbolAddress((void**)&wvl, g_wvl);
    cudaGetSymbolAddress((void**)&woh, g_woh); cudaGetSymbolAddress((void**)&wol, g_wol);
    cudaGetSymbolAddress((void**)&w1h, g_w1h); cudaGetSymbolAddress((void**)&w1l, g_w1l);
    cudaGetSymbolAddress((void**)&w2h, g_w2h); cudaGetSymbolAddress((void**)&w2l, g_w2l);

    cudaFuncSetAttribute(tc_gemm<0>, cudaFuncAttributeMaxDynamicSharedMemorySize, DSMEM_SZ);
    cudaFuncSetAttribute(tc_gemm<1>, cudaFuncAttributeMaxDynamicSharedMemorySize, DSMEM_SZ);
    cudaFuncSetAttribute(tc_gemm<2>, cudaFuncAttributeMaxDynamicSharedMemorySize, DSMEM_SZ);
    cudaFuncSetAttribute(tc_gemm<3>, cudaFuncAttributeMaxDynamicSharedMemorySize, DSMEM_SZ);

    // weight transpose + split
    wsplitT<<<dim3(1024/32, 1024/32), 256>>>(Wq, wqh, wql, 1024, 1024);
    wsplitT<<<dim3(1024/32, 1024/32), 256>>>(Wk, wkh, wkl, 1024, 1024);
    wsplitT<<<dim3(1024/32, 1024/32), 256>>>(Wv, wvh, wvl, 1024, 1024);
    wsplitT<<<dim3(1024/32, 1024/32), 256>>>(Wo, woh, wol, 1024, 1024);
    wsplitT<<<dim3(4096/32, 1024/32), 256>>>(W1, w1h, w1l, 1024, 4096);
    wsplitT<<<dim3(1024/32, 4096/32), 256>>>(W2, w2h, w2l, 4096, 1024);

    // 1. ln1 (fp32 + split)
    ln_kernel<1><<<M_, 256>>>(x, ln1w, ln1b, n_, nhi, nlo);

    // 2-4. q/k/v projections (HMMA)
    dim3 g1(1024/128, M_/128);   // (8, 128)
    tc_gemm<0><<<g1, 256, DSMEM_SZ>>>(nhi, nlo, wqh, wql, nullptr, nullptr, q_, nullptr, nullptr, M_, 1024, 1024);
    tc_gemm<0><<<g1, 256, DSMEM_SZ>>>(nhi, nlo, wkh, wkl, nullptr, nullptr, k_, nullptr, nullptr, M_, 1024, 1024);
    tc_gemm<0><<<g1, 256, DSMEM_SZ>>>(nhi, nlo, wvh, wvl, nullptr, nullptr, v_, nullptr, nullptr, M_, 1024, 1024);

    // 5. alpha/beta
    ab_kernel<<<M_, 128>>>(n_, Wb, Wa, al_, be_);

    // 6. activations + l2norm
    act_qkv_kernel<<<M_*H_, 128>>>(q_, k_, v_);

    // 7. recurrence
    recur_kernel<<<B_*H_*4, 128>>>(q_, k_, v_, al_, be_, o_);

    // split o for Wo GEMM
    split_kernel<<<(M_*1024/4 + 255)/256, 256>>>(o_, ohi, olo, M_*1024/4);

    // 8. output projection + residual
    tc_gemm<1><<<g1, 256, DSMEM_SZ>>>(ohi, olo, woh, wol, nullptr, x, x1_, nullptr, nullptr, M_, 1024, 1024);

    // 9. ln2 (split only)
    ln_kernel<2><<<M_, 256>>>(x1_, ln2w, ln2b, nullptr, hhi, hlo);

    // 10. FFN up: +bias, GELU, emit bf16 hi/lo directly
    dim3 g2(4096/128, M_/128);   // (32, 128)
    tc_gemm<2><<<g2, 256, DSMEM_SZ>>>(hhi, hlo, w1h, w1l, b1, nullptr, nullptr, fhi, flo, M_, 4096, 1024);

    // 11. FFN down: +bias +resid
    tc_gemm<3><<<g1, 256, DSMEM_SZ>>>(fhi, flo, w2h, w2l, b2, x1_, out, nullptr, nullptr, M_, 1024, 4096);
}

// round 6
// speedup vs baseline: 2.5817x; 1.4589x over previous
#include <cuda_runtime.h>
#include <cuda_fp16.h>
#include <math.h>
#include <stdint.h>

#define B_ 4
#define T_ 4096
#define D_ 1024
#define H_ 8
#define K_ 128
#define V_ 128
#define F_ 4096
#define M_ (B_*T_)   // 16384 rows

// ---------------- scratch (device globals; no runtime allocation) ----------------
__device__ __align__(128) __half g_nh[(size_t)M_*D_];        // ln1 output fp16
__device__ __align__(128) float g_q [(size_t)M_*H_*K_];
__device__ __align__(128) float g_k [(size_t)M_*H_*K_];
__device__ __align__(128) float g_v [(size_t)M_*H_*V_];
__device__ __align__(128) float g_al[(size_t)M_*H_];
__device__ __align__(128) float g_be[(size_t)M_*H_];
__device__ __align__(128) float g_o [(size_t)M_*H_*V_];
__device__ __align__(128) __half g_oh[(size_t)M_*H_*V_];
__device__ __align__(128) float g_x1[(size_t)M_*D_];
__device__ __align__(128) __half g_hh[(size_t)M_*D_];
__device__ __align__(128) __half g_fh[(size_t)M_*F_];
// transposed weights ([N,K] K-major, fp16)
__device__ __align__(128) __half g_wq[1024*1024];
__device__ __align__(128) __half g_wk[1024*1024];
__device__ __align__(128) __half g_wv[1024*1024];
__device__ __align__(128) __half g_wo[1024*1024];
__device__ __align__(128) __half g_w1[(size_t)4096*1024];
__device__ __align__(128) __half g_w2[(size_t)1024*4096];

// ======================== PTX helpers ========================
__device__ __forceinline__ uint32_t smem_u32(const void* p) {
    uint32_t a;
    asm("{ .reg .u64 t; cvta.to.shared.u64 t, %1; cvt.u32.u64 %0, t; }" : "=r"(a) : "l"(p));
    return a;
}
__device__ __forceinline__ void cp16(uint32_t s, const void* g) {
    asm volatile("cp.async.cg.shared.global [%0], [%1], 16;\n" :: "r"(s), "l"(g));
}
__device__ __forceinline__ void cp_commit() { asm volatile("cp.async.commit_group;\n" ::: "memory"); }
template<int N> __device__ __forceinline__ void cp_wait() {
    asm volatile("cp.async.wait_group %0;\n" :: "n"(N) : "memory");
}
__device__ __forceinline__ void ldsm4(uint32_t& r0, uint32_t& r1, uint32_t& r2, uint32_t& r3, uint32_t addr) {
    asm volatile("ldmatrix.sync.aligned.m8n8.x4.shared.b16 {%0,%1,%2,%3}, [%4];"
        : "=r"(r0), "=r"(r1), "=r"(r2), "=r"(r3) : "r"(addr));
}
__device__ __forceinline__ void mma16816(float* d, const uint32_t* a, const uint32_t* b) {
    asm volatile("mma.sync.aligned.m16n8k16.row.col.f32.f16.f16.f32 "
        "{%0,%1,%2,%3},{%4,%5,%6,%7},{%8,%9},{%0,%1,%2,%3};"
        : "+f"(d[0]), "+f"(d[1]), "+f"(d[2]), "+f"(d[3])
        : "r"(a[0]), "r"(a[1]), "r"(a[2]), "r"(a[3]), "r"(b[0]), "r"(b[1]));
}

// ======================== HMMA GEMM (single-pass fp16) ========================
// C[M,N] = A[M,Kd] @ W[Kd,N]; A fp16 [M,Kd]; B transposed fp16 [N,Kd].
// Tiles: 128x128x32, 8 warps (4m x 2n), warp tile 32x64.
// Smem rows padded to 80B (5x16B) -> ldmatrix 8-row phases conflict-free.
// EPI: 0=plain fp32, 1=+resid, 2=+bias+GELU -> fp16, 3=+bias+resid
#define ROWB 80                      // padded row bytes (32 fp16 data = 64B + 16B pad)
#define ARR_B (128*ROWB)             // 10240 B per array
#define STG_B (2*ARR_B)              // 20480 B per stage (A + B)
#define NSTAGE 3
#define DSMEM_SZ (NSTAGE*STG_B + 1024)

template<int EPI>
__global__ __launch_bounds__(256, 1) void tc_gemm(
    const __half* __restrict__ A, const __half* __restrict__ Bw,
    const float* __restrict__ bias, const float* __restrict__ resid,
    float* __restrict__ C, __half* __restrict__ Ch,
    int M, int N, int Kd)
{
    extern __shared__ __align__(1024) char dsm_raw[];
    const int tid = threadIdx.x;
    const int wid = tid >> 5, lane = tid & 31;
    const int row0 = blockIdx.y * 128;
    const int col0 = blockIdx.x * 128;
    const int NC = Kd >> 5;              // chunks of 32 K-elements

    uint32_t sbase = smem_u32(dsm_raw);
    sbase = (sbase + 1023) & ~1023u;

    const int wm0 = (wid >> 1) * 32;
    const int wn0 = (wid & 1) * 64;

    float acc[2][8][4];
    #pragma unroll
    for (int i = 0; i < 2; i++)
        #pragma unroll
        for (int j = 0; j < 8; j++)
            #pragma unroll
            for (int r = 0; r < 4; r++) acc[i][j][r] = 0.f;

    // per-chunk load: 2 arrays x 128 rows x 64B data (80B pitch) = 4 cp16/thread
    auto load_chunk = [&](int c) {
        const int kb = c << 5;
        const uint32_t sb = sbase + (c % NSTAGE) * STG_B;
        #pragma unroll
        for (int arr = 0; arr < 2; arr++) {
            const __half* src = (arr == 0) ? A : Bw;
            const int rb = (arr == 0) ? row0 : col0;
            #pragma unroll
            for (int i2 = 0; i2 < 2; i2++) {
                int idx = tid + i2 * 256;            // 0..511
                int row = idx >> 2, seg = idx & 3;
                cp16(sb + arr * ARR_B + row * ROWB + seg * 16,
                     src + (size_t)(rb + row) * Kd + kb + seg * 8);
            }
        }
        cp_commit();
    };

    load_chunk(0);
    load_chunk(1);

    const int sub = lane >> 3, r8 = lane & 7;

    for (int c = 0; c < NC; c++) {
        if (c + 2 < NC) load_chunk(c + 2);
        if (c + 2 < NC) cp_wait<2>();
        else if (c + 1 < NC) cp_wait<1>();
        else cp_wait<0>();
        __syncthreads();

        const uint32_t sb = sbase + (c % NSTAGE) * STG_B;
        #pragma unroll
        for (int kk = 0; kk < 2; kk++) {             // two k16 steps per chunk
            const int kbyte = kk * 32;
            uint32_t af[2][4];
            #pragma unroll
            for (int mi = 0; mi < 2; mi++) {
                int row = wm0 + mi * 16 + (sub & 1) * 8 + r8;
                uint32_t off = row * ROWB + kbyte + (sub >> 1) * 16;
                ldsm4(af[mi][0], af[mi][1], af[mi][2], af[mi][3], sb + off);
            }
            uint32_t bf[8][2];
            #pragma unroll
            for (int nj = 0; nj < 4; nj++) {
                int row = wn0 + nj * 16 + (sub >> 1) * 8 + r8;
                uint32_t off = row * ROWB + kbyte + (sub & 1) * 16;
                ldsm4(bf[nj*2][0], bf[nj*2][1], bf[nj*2+1][0], bf[nj*2+1][1], sb + ARR_B + off);
            }
            #pragma unroll
            for (int mi = 0; mi < 2; mi++)
                #pragma unroll
                for (int ni = 0; ni < 8; ni++)
                    mma16816(acc[mi][ni], af[mi], bf[ni]);
        }
        __syncthreads();
    }

    // ---------------- epilogue ----------------
    const int bcol = col0 + wn0;
    float2 bv[8];
    if (EPI == 2 || EPI == 3) {
        #pragma unroll
        for (int ni = 0; ni < 8; ni++)
            bv[ni] = *(const float2*)(bias + bcol + ni * 8 + (lane & 3) * 2);
    }
    #pragma unroll
    for (int mi = 0; mi < 2; mi++) {
        #pragma unroll
        for (int hf = 0; hf < 2; hf++) {
            const int row = row0 + wm0 + mi * 16 + (lane >> 2) + hf * 8;
            #pragma unroll
            for (int ni = 0; ni < 8; ni++) {
                const int col = bcol + ni * 8 + (lane & 3) * 2;
                float y0 = acc[mi][ni][hf * 2];
                float y1 = acc[mi][ni][hf * 2 + 1];
                if (EPI == 2 || EPI == 3) { y0 += bv[ni].x; y1 += bv[ni].y; }
                if (EPI == 2) {
                    y0 = 0.5f * y0 * (1.f + erff(y0 * 0.70710678118f));
                    y1 = 0.5f * y1 * (1.f + erff(y1 * 0.70710678118f));
                }
                if (EPI == 1 || EPI == 3) {
                    float2 rv = *(const float2*)(resid + (size_t)row * N + col);
                    y0 += rv.x; y1 += rv.y;
                }
                if (EPI == 2) {
                    __half2 hh(__float2half_rn(y0), __float2half_rn(y1));
                    *(uint32_t*)(Ch + (size_t)row * N + col) = *(uint32_t*)&hh;
                } else {
                    *(float2*)(C + (size_t)row * N + col) = make_float2(y0, y1);
                }
            }
        }
    }
}

// ---------------- LayerNorm -> fp16 (and optionally nothing else) ----------------
__global__ __launch_bounds__(256) void ln_kernel(const float* __restrict__ x,
    const float* __restrict__ w, const float* __restrict__ bb,
    __half* __restrict__ oh)
{
    __shared__ float rs[8], rs2[8];
    int row = blockIdx.x, tid = threadIdx.x;
    const float4* xr = (const float4*)(x + (size_t)row * D_);
    float4 v = xr[tid];
    float s  = v.x + v.y + v.z + v.w;
    float s2 = v.x*v.x + v.y*v.y + v.z*v.z + v.w*v.w;
    #pragma unroll
    for (int m = 16; m; m >>= 1) {
        s  += __shfl_xor_sync(~0u, s,  m);
        s2 += __shfl_xor_sync(~0u, s2, m);
    }
    if ((tid & 31) == 0) { rs[tid>>5] = s; rs2[tid>>5] = s2; }
    __syncthreads();
    s = 0.f; s2 = 0.f;
    #pragma unroll
    for (int i = 0; i < 8; i++) { s += rs[i]; s2 += rs2[i]; }
    float mean = s * (1.0f/D_);
    float var  = s2 * (1.0f/D_) - mean*mean;
    float inv  = rsqrtf(var + 1e-5f);
    float4 wv = ((const float4*)w)[tid];
    float4 bv = ((const float4*)bb)[tid];
    float o0 = (v.x-mean)*inv*wv.x + bv.x;
    float o1 = (v.y-mean)*inv*wv.y + bv.y;
    float o2 = (v.z-mean)*inv*wv.z + bv.z;
    float o3 = (v.w-mean)*inv*wv.w + bv.w;
    __half2 h0(__float2half_rn(o0), __float2half_rn(o1));
    __half2 h1(__float2half_rn(o2), __float2half_rn(o3));
    ((uint2*)(oh + (size_t)row * D_))[tid] = make_uint2(*(uint32_t*)&h0, *(uint32_t*)&h1);
}

// ---------------- weight transpose: W[K,N] fp32 -> [N,K] fp16 ----------------
__global__ __launch_bounds__(256) void wconvT(const float* __restrict__ W,
    __half* __restrict__ WT, int Kd, int N)
{
    __shared__ float t[32][33];
    int n0 = blockIdx.x * 32, k0 = blockIdx.y * 32;
    int tx = threadIdx.x & 31, ty = threadIdx.x >> 5;
    #pragma unroll
    for (int i = 0; i < 4; i++)
        t[ty + 8*i][tx] = W[(size_t)(k0 + ty + 8*i) * N + n0 + tx];
    __syncthreads();
    #pragma unroll
    for (int i = 0; i < 4; i++)
        WT[(size_t)(n0 + ty + 8*i) * Kd + k0 + tx] = __float2half_rn(t[tx][ty + 8*i]);
}

// ---------------- elementwise fp32 -> fp16 ----------------
__global__ __launch_bounds__(256) void conv_kernel(const float* __restrict__ x,
    __half* __restrict__ h, int n4)
{
    int i = blockIdx.x * 256 + threadIdx.x;
    if (i >= n4) return;
    float4 v = ((const float4*)x)[i];
    __half2 h0(__float2half_rn(v.x), __float2half_rn(v.y));
    __half2 h1(__float2half_rn(v.z), __float2half_rn(v.w));
    ((uint2*)h)[i] = make_uint2(*(uint32_t*)&h0, *(uint32_t*)&h1);
}

// ---------------- alpha/beta: sigmoid(n @ W{a,b}), from fp16 n ----------------
__global__ __launch_bounds__(128) void ab_kernel(const __half* __restrict__ n,
    const float* __restrict__ Wb, const float* __restrict__ Wa,
    float* __restrict__ al, float* __restrict__ be)
{
    int row = blockIdx.x, tid = threadIdx.x;
    int g = tid >> 3, l = tid & 7;
    const float* W = (g < 8) ? Wb : Wa;
    int c = g & 7;
    const __half* nr = n + (size_t)row * D_;
    float s = 0.f;
    for (int d = l; d < D_; d += 8) s = fmaf(__half2float(nr[d]), W[d*H_ + c], s);
    s += __shfl_xor_sync(~0u, s, 1);
    s += __shfl_xor_sync(~0u, s, 2);
    s += __shfl_xor_sync(~0u, s, 4);
    if (l == 0) {
        float sig = 1.f/(1.f + expf(-s));
        if (g < 8) be[(size_t)row*H_ + c] = sig;
        else       al[(size_t)row*H_ + c] = sig;
    }
}

// ---------------- silu + l2norm on q,k; silu on v ----------------
__global__ __launch_bounds__(128) void act_qkv_kernel(float* __restrict__ q,
    float* __restrict__ kk, float* __restrict__ v)
{
    __shared__ float rq[4], rk[4];
    int row = blockIdx.x, tid = threadIdx.x;
    size_t idx = (size_t)row*128 + tid;
    float xq = q[idx], xk = kk[idx], xv = v[idx];
    float yq = xq / (1.f + expf(-xq));
    float yk = xk / (1.f + expf(-xk));
    float sq = yq*yq, sk2 = yk*yk;
    #pragma unroll
    for (int m = 16; m; m >>= 1) {
        sq  += __shfl_xor_sync(~0u, sq,  m);
        sk2 += __shfl_xor_sync(~0u, sk2, m);
    }
    if ((tid & 31) == 0) { rq[tid>>5] = sq; rk[tid>>5] = sk2; }
    __syncthreads();
    float nq = rq[0]+rq[1]+rq[2]+rq[3];
    float nk = rk[0]+rk[1]+rk[2]+rk[3];
    q[idx]  = yq * rsqrtf(nq + 1e-6f);
    kk[idx] = yk * rsqrtf(nk + 1e-6f);
    v[idx]  = xv / (1.f + expf(-xv));
}

// ---------------- gated delta-rule recurrence ----------------
__global__ __launch_bounds__(128) void recur_kernel(
    const float* __restrict__ q, const float* __restrict__ k, const float* __restrict__ v,
    const float* __restrict__ al, const float* __restrict__ be, float* __restrict__ o)
{
    __shared__ __align__(16) float sk[2][152];
    __shared__ __align__(16) float sq[2][152];
    __shared__ float sv[2][32];
    __shared__ float sab[2][2];

    int blk = blockIdx.x;
    int bh = blk >> 2, split = blk & 3;
    int b = bh >> 3, h = bh & 7;
    int tid = threadIdx.x;
    int col = tid >> 2, r4 = tid & 3;
    int skewIdx = ((tid >> 5) * 36) + (tid & 31);
    int rbase = r4 * 36;
    size_t base  = ((size_t)b * T_ * H_ + h) * (size_t)K_;
    size_t abase = ((size_t)b * T_) * H_ + h;

    float S[32];
    #pragma unroll
    for (int i = 0; i < 32; i++) S[i] = 0.f;

    sk[0][skewIdx] = k[base + tid];
    sq[0][skewIdx] = q[base + tid];
    if (tid < 32) sv[0][tid] = v[base + split*32 + tid];
    if (tid == 0) { sab[0][0] = al[abase]; sab[0][1] = be[abase]; }
    __syncthreads();

    int buf = 0;
    for (int t = 0; t < T_; t++) {
        float pk = 0.f, pq = 0.f, pv = 0.f, pa = 0.f, pb = 0.f;
        if (t + 1 < T_) {
            size_t off = base + (size_t)(t+1) * (H_*K_);
            pk = k[off + tid];
            pq = q[off + tid];
            if (tid < 32) pv = v[off + split*32 + tid];
            if (tid == 0) {
                pa = al[abase + (size_t)(t+1)*H_];
                pb = be[abase + (size_t)(t+1)*H_];
            }
        }
        float kreg[32];
        float kv0=0.f,kv1=0.f,kv2=0.f,kv3=0.f;
        #pragma unroll
        for (int i4 = 0; i4 < 8; i4++) {
            float4 k4 = *(const float4*)(&sk[buf][rbase + i4*4]);
            kreg[i4*4+0]=k4.x; kreg[i4*4+1]=k4.y; kreg[i4*4+2]=k4.z; kreg[i4*4+3]=k4.w;
            kv0 = fmaf(k4.x, S[i4*4+0], kv0);
            kv1 = fmaf(k4.y, S[i4*4+1], kv1);
            kv2 = fmaf(k4.z, S[i4*4+2], kv2);
            kv3 = fmaf(k4.w, S[i4*4+3], kv3);
        }
        float kv = (kv0+kv1)+(kv2+kv3);
        kv += __shfl_xor_sync(~0u, kv, 1);
        kv += __shfl_xor_sync(~0u, kv, 2);
        float a  = sab[buf][0], bt = sab[buf][1];
        float w  = bt * (sv[buf][col] - a * kv);
        #pragma unroll
        for (int i = 0; i < 32; i++) S[i] = fmaf(a, S[i], kreg[i]*w);
        float o0=0.f,o1=0.f,o2=0.f,o3=0.f;
        #pragma unroll
        for (int i4 = 0; i4 < 8; i4++) {
            float4 q4 = *(const float4*)(&sq[buf][rbase + i4*4]);
            o0 = fmaf(q4.x, S[i4*4+0], o0);
            o1 = fmaf(q4.y, S[i4*4+1], o1);
            o2 = fmaf(q4.z, S[i4*4+2], o2);
            o3 = fmaf(q4.w, S[i4*4+3], o3);
        }
        float oa = (o0+o1)+(o2+o3);
        oa += __shfl_xor_sync(~0u, oa, 1);
        oa += __shfl_xor_sync(~0u, oa, 2);
        if (r4 == 0) o[base + (size_t)t*(H_*K_) + split*32 + col] = oa;
        int nb = buf ^ 1;
        if (t + 1 < T_) {
            sk[nb][skewIdx] = pk;
            sq[nb][skewIdx] = pq;
            if (tid < 32) sv[nb][tid] = pv;
            if (tid == 0) { sab[nb][0] = pa; sab[nb][1] = pb; }
        }
        __syncthreads();
        buf = nb;
    }
}

// ---------------- launch ----------------
extern "C" void kernel_launch(void* const* d_in, const int* in_sizes, int n_in,
                              void* d_out, int out_size)
{
    const float* x    = (const float*)d_in[0];
    const float* Wq   = (const float*)d_in[1];
    const float* Wk   = (const float*)d_in[2];
    const float* Wv   = (const float*)d_in[3];
    const float* Wb   = (const float*)d_in[4];
    const float* Wa   = (const float*)d_in[5];
    const float* Wo   = (const float*)d_in[6];
    const float* ln1w = (const float*)d_in[7];
    const float* ln1b = (const float*)d_in[8];
    const float* ln2w = (const float*)d_in[9];
    const float* ln2b = (const float*)d_in[10];
    const float* W1   = (const float*)d_in[11];
    const float* b1   = (const float*)d_in[12];
    const float* W2   = (const float*)d_in[13];
    const float* b2   = (const float*)d_in[14];
    float* out = (float*)d_out;

    float *q_, *k_, *v_, *al_, *be_, *o_, *x1_;
    __half *nh, *oh, *hh, *fh, *wq, *wk, *wv, *wo, *w1, *w2;
    cudaGetSymbolAddress((void**)&nh,  g_nh);
    cudaGetSymbolAddress((void**)&q_,  g_q);
    cudaGetSymbolAddress((void**)&k_,  g_k);
    cudaGetSymbolAddress((void**)&v_,  g_v);
    cudaGetSymbolAddress((void**)&al_, g_al);
    cudaGetSymbolAddress((void**)&be_, g_be);
    cudaGetSymbolAddress((void**)&o_,  g_o);
    cudaGetSymbolAddress((void**)&oh,  g_oh);
    cudaGetSymbolAddress((void**)&x1_, g_x1);
    cudaGetSymbolAddress((void**)&hh,  g_hh);
    cudaGetSymbolAddress((void**)&fh,  g_fh);
    cudaGetSymbolAddress((void**)&wq,  g_wq);
    cudaGetSymbolAddress((void**)&wk,  g_wk);
    cudaGetSymbolAddress((void**)&wv,  g_wv);
    cudaGetSymbolAddress((void**)&wo,  g_wo);
    cudaGetSymbolAddress((void**)&w1,  g_w1);
    cudaGetSymbolAddress((void**)&w2,  g_w2);

    cudaFuncSetAttribute(tc_gemm<0>, cudaFuncAttributeMaxDynamicSharedMemorySize, DSMEM_SZ);
    cudaFuncSetAttribute(tc_gemm<1>, cudaFuncAttributeMaxDynamicSharedMemorySize, DSMEM_SZ);
    cudaFuncSetAttribute(tc_gemm<2>, cudaFuncAttributeMaxDynamicSharedMemorySize, DSMEM_SZ);
    cudaFuncSetAttribute(tc_gemm<3>, cudaFuncAttributeMaxDynamicSharedMemorySize, DSMEM_SZ);

    // weight transpose + fp16 convert
    wconvT<<<dim3(1024/32, 1024/32), 256>>>(Wq, wq, 1024, 1024);
    wconvT<<<dim3(1024/32, 1024/32), 256>>>(Wk, wk, 1024, 1024);
    wconvT<<<dim3(1024/32, 1024/32), 256>>>(Wv, wv, 1024, 1024);
    wconvT<<<dim3(1024/32, 1024/32), 256>>>(Wo, wo, 1024, 1024);
    wconvT<<<dim3(4096/32, 1024/32), 256>>>(W1, w1, 1024, 4096);
    wconvT<<<dim3(1024/32, 4096/32), 256>>>(W2, w2, 4096, 1024);

    // 1. ln1 -> fp16
    ln_kernel<<<M_, 256>>>(x, ln1w, ln1b, nh);

    // 2-4. q/k/v projections (fp16 HMMA)
    dim3 g1(1024/128, M_/128);   // (8, 128)
    tc_gemm<0><<<g1, 256, DSMEM_SZ>>>(nh, wq, nullptr, nullptr, q_, nullptr, M_, 1024, 1024);
    tc_gemm<0><<<g1, 256, DSMEM_SZ>>>(nh, wk, nullptr, nullptr, k_, nullptr, M_, 1024, 1024);
    tc_gemm<0><<<g1, 256, DSMEM_SZ>>>(nh, wv, nullptr, nullptr, v_, nullptr, M_, 1024, 1024);

    // 5. alpha/beta
    ab_kernel<<<M_, 128>>>(nh, Wb, Wa, al_, be_);

    // 6. activations + l2norm
    act_qkv_kernel<<<M_*H_, 128>>>(q_, k_, v_);

    // 7. recurrence
    recur_kernel<<<B_*H_*4, 128>>>(q_, k_, v_, al_, be_, o_);

    // convert o for Wo GEMM
    conv_kernel<<<(M_*1024/4 + 255)/256, 256>>>(o_, oh, M_*1024/4);

    // 8. output projection + residual
    tc_gemm<1><<<g1, 256, DSMEM_SZ>>>(oh, wo, nullptr, x, x1_, nullptr, M_, 1024, 1024);

    // 9. ln2 -> fp16
    ln_kernel<<<M_, 256>>>(x1_, ln2w, ln2b, hh);

    // 10. FFN up: +bias, GELU, emit fp16
    dim3 g2(4096/128, M_/128);   // (32, 128)
    tc_gemm<2><<<g2, 256, DSMEM_SZ>>>(hh, w1, b1, nullptr, nullptr, fh, M_, 4096, 1024);

    // 11. FFN down: +bias +resid
    tc_gemm<3><<<g1, 256, DSMEM_SZ>>>(fh, w2, b2, x1_, out, nullptr, M_, 1024, 4096);
}